// round 4
// baseline (speedup 1.0000x reference)
#include <cuda_runtime.h>
#include <cuda_bf16.h>

// ---------------- problem constants ----------------
#define NPOS  (512*512)   // 262144 spatial positions
#define CDIM  64
#define ADIM  128
#define HIDN  256
#define NACT  4

// ---------------- scratch (device globals; no allocation) ----------------
__device__ __nv_bfloat16 g_featT[(size_t)ADIM * NPOS]; // [a][n]  64 MB
__device__ float g_scores[NPOS];
__device__ int   g_smax;                   // ordered-int float max
__device__ float g_gates[4 * HIDN];
__device__ float g_h[HIDN];
__device__ float g_c[HIDN];
__device__ __nv_bfloat16 g_w1b[ADIM * CDIM];
__device__ __nv_bfloat16 g_iawb[ADIM * ADIM];
__device__ float g_Upart[256 * ADIM];
__device__ float g_Zpart[256];

// ordered-int mapping for atomicMax on float (monotone, deterministic)
__device__ __forceinline__ int f2o(float f) {
    int i = __float_as_int(f);
    return i >= 0 ? i : (i ^ 0x7FFFFFFF);
}
__device__ __forceinline__ float o2f(int o) {
    return __int_as_float(o >= 0 ? o : (o ^ 0x7FFFFFFF));
}

__device__ __forceinline__ unsigned s2u(const void* p) {
    return (unsigned)__cvta_generic_to_shared(p);
}

// ---------------- kernel W: convert weights to bf16 ----------------
__global__ void kweights(const float* __restrict__ conv_w, const float* __restrict__ ia_w) {
    int idx = blockIdx.x * blockDim.x + threadIdx.x;
    if (idx < ADIM * CDIM) g_w1b[idx]  = __float2bfloat16(conv_w[idx]);
    if (idx < ADIM * ADIM) g_iawb[idx] = __float2bfloat16(ia_w[idx]);
}

// ---------------- kernel A1: LSTM gates (grid=32, 256 thr) ----------------
__global__ void klstm_gates(const float* __restrict__ action, const float* __restrict__ ae_w,
                            const float* __restrict__ ae_b, const float* __restrict__ h0,
                            const float* __restrict__ w_ih, const float* __restrict__ w_hh,
                            const float* __restrict__ b_ih, const float* __restrict__ b_hh) {
    __shared__ float xs[HIDN], h0s[HIDN];
    int tid = threadIdx.x;
    if (tid < HIDN) {
        float acc = ae_b[tid];
#pragma unroll
        for (int j = 0; j < NACT; j++) acc = fmaf(ae_w[tid * NACT + j], action[j], acc);
        xs[tid]  = acc;
        h0s[tid] = h0[tid];
    }
    if (blockIdx.x == 0 && tid == 0) g_smax = (int)0x80000000; // INT_MIN init for atomicMax
    __syncthreads();
    int wid = tid >> 5, lane = tid & 31;
#pragma unroll
    for (int rr = 0; rr < 4; rr++) {
        int r = blockIdx.x * 32 + wid * 4 + rr;
        const float* wi = w_ih + (size_t)r * HIDN;
        const float* wh = w_hh + (size_t)r * HIDN;
        float acc = 0.f;
        for (int j = lane; j < HIDN; j += 32)
            acc = fmaf(wi[j], xs[j], fmaf(wh[j], h0s[j], acc));
#pragma unroll
        for (int s = 16; s; s >>= 1) acc += __shfl_xor_sync(0xffffffffu, acc, s);
        if (lane == 0) g_gates[r] = acc + b_ih[r] + b_hh[r];
    }
}

// ---------------- kernel A2: LSTM cell; writes h,c to out ----------------
__global__ void klstm_cell(const float* __restrict__ c0, float* __restrict__ out) {
    int t = threadIdx.x; // 256 threads
    float gi = g_gates[t], gf = g_gates[HIDN + t], gg = g_gates[2 * HIDN + t], go = g_gates[3 * HIDN + t];
    float si = 1.f / (1.f + expf(-gi));
    float sf = 1.f / (1.f + expf(-gf));
    float so = 1.f / (1.f + expf(-go));
    float c = sf * c0[t] + si * tanhf(gg);
    float h = so * tanhf(c);
    g_h[t] = h; g_c[t] = c;
    out[4 + t]        = h;
    out[4 + HIDN + t] = c;
}

// ---------------- main kernel smem layout (dynamic) ----------------
#define OFF_IMG 0                      // 64  x 136 bf16  = 17408
#define OFF_W1  17408                  // 128 x 72  bf16  = 18432
#define OFF_IA  35840                  // 128 x 136 bf16  = 34816
#define OFF_FT  70656                  // 128 x 136 bf16  = 34816
#define OFF_SP  105472                 // 4 x 128 f32     = 2048
#define OFF_CB  107520                 // 128 f32
#define OFF_IABV 108032                // 128 f32
#define OFF_FA  108544                 // 128 f32
#define OFF_RED 109056                 // 16 f32
#define DSMEM_B 109120

// 16x8x16 bf16 mma, A row-major (from ldmatrix), B col-major (from ldmatrix.trans)
template <int K>
__device__ __forceinline__ void gemm_tile(
    float (&acc)[2][8][4], unsigned Abase, int AstrideB, unsigned Bbase,
    int mrow0, int ncol0, int a_row, int a_koff, int b_row, int b_col)
{
#pragma unroll
    for (int k0 = 0; k0 < K; k0 += 16) {
        unsigned a[2][4];
#pragma unroll
        for (int mt = 0; mt < 2; mt++) {
            unsigned addr = Abase + (unsigned)((mrow0 + mt * 16 + a_row) * AstrideB + (k0 + a_koff) * 2);
            asm volatile("ldmatrix.sync.aligned.m8n8.x4.shared.b16 {%0,%1,%2,%3}, [%4];"
                         : "=r"(a[mt][0]), "=r"(a[mt][1]), "=r"(a[mt][2]), "=r"(a[mt][3]) : "r"(addr));
        }
        unsigned b[4][4];
#pragma unroll
        for (int np = 0; np < 4; np++) {
            unsigned addr = Bbase + (unsigned)((k0 + b_row) * 272 + (ncol0 + np * 16 + b_col) * 2);
            asm volatile("ldmatrix.sync.aligned.m8n8.x4.trans.shared.b16 {%0,%1,%2,%3}, [%4];"
                         : "=r"(b[np][0]), "=r"(b[np][1]), "=r"(b[np][2]), "=r"(b[np][3]) : "r"(addr));
        }
#pragma unroll
        for (int mt = 0; mt < 2; mt++)
#pragma unroll
            for (int nt = 0; nt < 8; nt++) {
                int np = nt >> 1;
                unsigned b0 = (nt & 1) ? b[np][1] : b[np][0];
                unsigned b1 = (nt & 1) ? b[np][3] : b[np][2];
                asm volatile(
                    "mma.sync.aligned.m16n8k16.row.col.f32.bf16.bf16.f32 "
                    "{%0,%1,%2,%3}, {%4,%5,%6,%7}, {%8,%9}, {%0,%1,%2,%3};"
                    : "+f"(acc[mt][nt][0]), "+f"(acc[mt][nt][1]), "+f"(acc[mt][nt][2]), "+f"(acc[mt][nt][3])
                    : "r"(a[mt][0]), "r"(a[mt][1]), "r"(a[mt][2]), "r"(a[mt][3]), "r"(b0), "r"(b1));
            }
    }
}

// ---------------- kernel B: feat -> att1 -> scores (grid=2048, 256 thr) ----------------
__global__ void __launch_bounds__(256) kmain(const float* __restrict__ img,
                                             const float* __restrict__ conv_b,
                                             const float* __restrict__ ia_b,
                                             const float* __restrict__ fa_w) {
    extern __shared__ char sm[];
    __nv_bfloat162* simg = (__nv_bfloat162*)(sm + OFF_IMG);
    __nv_bfloat162* sw1  = (__nv_bfloat162*)(sm + OFF_W1);
    __nv_bfloat162* sia  = (__nv_bfloat162*)(sm + OFF_IA);
    __nv_bfloat162* sft  = (__nv_bfloat162*)(sm + OFF_FT);
    float* spart = (float*)(sm + OFF_SP);
    float* cb    = (float*)(sm + OFF_CB);
    float* iab   = (float*)(sm + OFF_IABV);
    float* fav   = (float*)(sm + OFF_FA);
    float* red   = (float*)(sm + OFF_RED);

    int tid = threadIdx.x;
    int n0  = blockIdx.x * 128;

    // ---- fill smem ----
    {   // img tile (64 x 128 f32 -> bf16), row stride 136 elems (68 words)
        const float* ib = img + n0;
        for (int i = tid; i < 64 * 64; i += 256) {
            int c = i >> 6, mw = i & 63;
            float2 v = *(const float2*)(ib + (size_t)c * NPOS + 2 * mw);
            __nv_bfloat162 b; b.x = __float2bfloat16_rn(v.x); b.y = __float2bfloat16_rn(v.y);
            simg[c * 68 + mw] = b;
        }
        for (int i = tid; i < 128 * 32; i += 256) { // conv_w bf16, stride 72 (36 words)
            int r = i >> 5, kw = i & 31;
            sw1[r * 36 + kw] = *(const __nv_bfloat162*)(g_w1b + r * CDIM + 2 * kw);
        }
        for (int i = tid; i < 128 * 64; i += 256) { // ia_w bf16, stride 136
            int r = i >> 6, kw = i & 63;
            sia[r * 68 + kw] = *(const __nv_bfloat162*)(g_iawb + r * ADIM + 2 * kw);
        }
        if (tid < 128) { cb[tid] = conv_b[tid]; iab[tid] = ia_b[tid]; fav[tid] = fa_w[tid]; }
    }
    __syncthreads();

    int wid = tid >> 5, lane = tid & 31;
    int mrow0 = (wid >> 1) * 32, ncol0 = (wid & 1) * 64;
    int lrow  = lane & 7;
    int a_row  = lrow + ((lane >> 3) & 1) * 8;
    int a_koff = (lane >> 4) * 8;
    int b_row  = lrow + (lane >> 4) * 8;
    int b_col  = ((lane >> 3) & 1) * 8;
    int g = lane >> 2, t = lane & 3;

    float acc[2][8][4] = {};

    // GEMM1: Feat^T (128 x 128) = conv_w (128x64) * img (64x128)
    gemm_tile<64>(acc, s2u(sw1), 144, s2u(simg), mrow0, ncol0, a_row, a_koff, b_row, b_col);

    // epilogue 1: +bias, relu, write bf16 Feat^T to smem; re-zero acc
#pragma unroll
    for (int mt = 0; mt < 2; mt++) {
        int r0 = mrow0 + mt * 16 + g, r1 = r0 + 8;
        float cb0 = cb[r0], cb1 = cb[r1];
#pragma unroll
        for (int nt = 0; nt < 8; nt++) {
            int col0 = ncol0 + nt * 8 + 2 * t;
            float v00 = fmaxf(acc[mt][nt][0] + cb0, 0.f);
            float v01 = fmaxf(acc[mt][nt][1] + cb0, 0.f);
            float v10 = fmaxf(acc[mt][nt][2] + cb1, 0.f);
            float v11 = fmaxf(acc[mt][nt][3] + cb1, 0.f);
            __nv_bfloat162 p0; p0.x = __float2bfloat16_rn(v00); p0.y = __float2bfloat16_rn(v01);
            __nv_bfloat162 p1; p1.x = __float2bfloat16_rn(v10); p1.y = __float2bfloat16_rn(v11);
            sft[r0 * 68 + (col0 >> 1)] = p0;
            sft[r1 * 68 + (col0 >> 1)] = p1;
            acc[mt][nt][0] = acc[mt][nt][1] = acc[mt][nt][2] = acc[mt][nt][3] = 0.f;
        }
    }
    __syncthreads();

    // copy Feat^T tile to global scratch (coalesced 32-bit)
    {
        const unsigned* ftw = (const unsigned*)(sm + OFF_FT);
        for (int i = tid; i < 128 * 64; i += 256) {
            int r = i >> 6, cw = i & 63;
            ((unsigned*)(g_featT + (size_t)r * NPOS + n0))[cw] = ftw[r * 68 + cw];
        }
    }

    // GEMM2: att1^T (128 x 128) = ia_w (128x128) * Feat^T
    gemm_tile<128>(acc, s2u(sia), 272, s2u(sft), mrow0, ncol0, a_row, a_koff, b_row, b_col);

    // epilogue 2: +bias, relu, multiply by fa_w[a], column-sum -> scores
    float sv[16];
#pragma unroll
    for (int k = 0; k < 16; k++) sv[k] = 0.f;
#pragma unroll
    for (int mt = 0; mt < 2; mt++) {
        int r0 = mrow0 + mt * 16 + g, r1 = r0 + 8;
        float ib0 = iab[r0], ib1 = iab[r1], f0 = fav[r0], f1 = fav[r1];
#pragma unroll
        for (int nt = 0; nt < 8; nt++) {
            float v00 = fmaxf(acc[mt][nt][0] + ib0, 0.f);
            float v01 = fmaxf(acc[mt][nt][1] + ib0, 0.f);
            float v10 = fmaxf(acc[mt][nt][2] + ib1, 0.f);
            float v11 = fmaxf(acc[mt][nt][3] + ib1, 0.f);
            sv[2 * nt]     += f0 * v00 + f1 * v10;
            sv[2 * nt + 1] += f0 * v01 + f1 * v11;
        }
    }
#pragma unroll
    for (int k = 0; k < 16; k++) {
        sv[k] += __shfl_xor_sync(0xffffffffu, sv[k], 4);
        sv[k] += __shfl_xor_sync(0xffffffffu, sv[k], 8);
        sv[k] += __shfl_xor_sync(0xffffffffu, sv[k], 16);
    }
    if (lane < 4) { // lanes 0..3 hold totals for their column pairs
        float* sp = spart + (wid >> 1) * 128;
#pragma unroll
        for (int nt = 0; nt < 8; nt++) {
            int c = ncol0 + nt * 8 + 2 * lane;
            sp[c]     = sv[2 * nt];
            sp[c + 1] = sv[2 * nt + 1];
        }
    }
    __syncthreads();
    if (tid < 128) {
        float s = spart[tid] + spart[128 + tid] + spart[256 + tid] + spart[384 + tid];
        g_scores[n0 + tid] = s;
        float m = s;
#pragma unroll
        for (int sh = 16; sh; sh >>= 1) m = fmaxf(m, __shfl_xor_sync(0xffffffffu, m, sh));
        if (lane == 0) red[wid] = m;
    }
    __syncthreads();
    if (tid == 0) {
        float m = fmaxf(fmaxf(red[0], red[1]), fmaxf(red[2], red[3]));
        atomicMax(&g_smax, f2o(m));
    }
}

// ---------------- kernel E: weighted sums (grid=256, 256 thr) ----------------
__global__ void __launch_bounds__(256) katt() {
    __shared__ float ws[1024];
    __shared__ float red2[8];
    int tid = threadIdx.x, n0 = blockIdx.x * 1024;
    int wid = tid >> 5, lane = tid & 31;
    float smaxv = o2f(g_smax);
    float zp = 0.f;
    for (int j = tid; j < 1024; j += 256) {
        float w = expf(g_scores[n0 + j] - smaxv);
        ws[j] = w; zp += w;
    }
#pragma unroll
    for (int s = 16; s; s >>= 1) zp += __shfl_xor_sync(0xffffffffu, zp, s);
    if (lane == 0) red2[wid] = zp;
    __syncthreads();
    if (tid == 0) {
        float z = 0.f;
#pragma unroll
        for (int w = 0; w < 8; w++) z += red2[w];
        g_Zpart[blockIdx.x] = z;
    }
    // per-a weighted sums; warp w handles a = w, w+8, ...
    for (int a = wid; a < ADIM; a += 8) {
        const __nv_bfloat162* row = (const __nv_bfloat162*)(g_featT + (size_t)a * NPOS + n0);
        float acc = 0.f;
        for (int i = lane; i < 512; i += 32) {
            __nv_bfloat162 v = row[i];
            float2 wv = *(const float2*)(ws + 2 * i);
            acc = fmaf(__low2float(v), wv.x, fmaf(__high2float(v), wv.y, acc));
        }
#pragma unroll
        for (int s = 16; s; s >>= 1) acc += __shfl_xor_sync(0xffffffffu, acc, s);
        if (lane == 0) g_Upart[blockIdx.x * ADIM + a] = acc;
    }
}

// ---------------- kernel F: final reduce + logits (1 block, 256 thr) ----------------
__global__ void kfinal(const float* __restrict__ actor_w, const float* __restrict__ actor_b,
                       float* __restrict__ out) {
    __shared__ float ao[ADIM];
    __shared__ float zsh;
    int tid = threadIdx.x;
    if (tid < 32) {
        float z = 0.f;
        for (int b = tid; b < 256; b += 32) z += g_Zpart[b];
#pragma unroll
        for (int s = 16; s; s >>= 1) z += __shfl_xor_sync(0xffffffffu, z, s);
        if (tid == 0) zsh = z;
    }
    __syncthreads();
    if (tid < ADIM) {
        float u = 0.f;
        for (int b = 0; b < 256; b++) u += g_Upart[b * ADIM + tid];
        ao[tid] = u / zsh;
    }
    __syncthreads();
    int wid = tid >> 5, lane = tid & 31;
    if (wid < 4) {
        const float* wrow = actor_w + (size_t)wid * (ADIM + HIDN);
        float acc = 0.f;
        for (int j = lane; j < ADIM + HIDN; j += 32) {
            float v = (j < ADIM) ? ao[j] : g_h[j - ADIM];
            acc = fmaf(wrow[j], v, acc);
        }
#pragma unroll
        for (int s = 16; s; s >>= 1) acc += __shfl_xor_sync(0xffffffffu, acc, s);
        if (lane == 0) out[wid] = acc + actor_b[wid];
    }
}

// ---------------- launcher ----------------
extern "C" void kernel_launch(void* const* d_in, const int* in_sizes, int n_in,
                              void* d_out, int out_size) {
    (void)in_sizes; (void)n_in; (void)out_size;
    const float* img     = (const float*)d_in[0];
    const float* action  = (const float*)d_in[1];
    const float* h0      = (const float*)d_in[2];
    const float* c0      = (const float*)d_in[3];
    const float* conv_w  = (const float*)d_in[4];
    const float* conv_b  = (const float*)d_in[5];
    const float* ae_w    = (const float*)d_in[6];
    const float* ae_b    = (const float*)d_in[7];
    const float* ia_w    = (const float*)d_in[8];
    const float* ia_b    = (const float*)d_in[9];
    // d_in[10] ha_w, d_in[11] ha_b, d_in[13] fa_b: constants cancel in softmax
    const float* fa_w    = (const float*)d_in[12];
    const float* w_ih    = (const float*)d_in[14];
    const float* w_hh    = (const float*)d_in[15];
    const float* b_ih    = (const float*)d_in[16];
    const float* b_hh    = (const float*)d_in[17];
    const float* actor_w = (const float*)d_in[18];
    const float* actor_b = (const float*)d_in[19];
    float* out = (float*)d_out;

    cudaFuncSetAttribute(kmain, cudaFuncAttributeMaxDynamicSharedMemorySize, DSMEM_B);

    kweights<<<64, 256>>>(conv_w, ia_w);
    klstm_gates<<<32, 256>>>(action, ae_w, ae_b, h0, w_ih, w_hh, b_ih, b_hh);
    klstm_cell<<<1, 256>>>(c0, out);
    kmain<<<NPOS / 128, 256, DSMEM_B>>>(img, conv_b, ia_b, fa_w);
    katt<<<NPOS / 1024, 256>>>();
    kfinal<<<1, 256>>>(actor_w, actor_b, out);
}

// round 6
// speedup vs baseline: 1.0842x; 1.0842x over previous
#include <cuda_runtime.h>
#include <cuda_bf16.h>

// ---------------- problem constants ----------------
#define NPOS  (512*512)   // 262144 spatial positions
#define CDIM  64
#define ADIM  128
#define HIDN  256
#define NACT  4

#define KATT_BLKS 1024
#define KATT_NP   256     // positions per katt block

// ---------------- scratch (device globals; no allocation) ----------------
__device__ __nv_bfloat16 g_featT[(size_t)ADIM * NPOS]; // [a][n]  64 MB
__device__ float g_scores[NPOS];
__device__ int   g_smax;                   // ordered-int float max
__device__ float g_gates[4 * HIDN];
__device__ float g_h[HIDN];
__device__ float g_c[HIDN];
__device__ __nv_bfloat16 g_w1b[ADIM * CDIM];
__device__ __nv_bfloat16 g_iawb[ADIM * ADIM];
__device__ float g_Upart[KATT_BLKS * ADIM];   // 512 KB
__device__ float g_Zpart[KATT_BLKS];

// ordered-int mapping for atomicMax on float (monotone, deterministic)
__device__ __forceinline__ int f2o(float f) {
    int i = __float_as_int(f);
    return i >= 0 ? i : (i ^ 0x7FFFFFFF);
}
__device__ __forceinline__ float o2f(int o) {
    return __int_as_float(o >= 0 ? o : (o ^ 0x7FFFFFFF));
}

__device__ __forceinline__ unsigned s2u(const void* p) {
    return (unsigned)__cvta_generic_to_shared(p);
}

// ---------------- kernel W: convert weights to bf16 ----------------
__global__ void kweights(const float* __restrict__ conv_w, const float* __restrict__ ia_w) {
    int idx = blockIdx.x * blockDim.x + threadIdx.x;
    if (idx < ADIM * CDIM) g_w1b[idx]  = __float2bfloat16(conv_w[idx]);
    if (idx < ADIM * ADIM) g_iawb[idx] = __float2bfloat16(ia_w[idx]);
}

// ---------------- kernel A1: LSTM gates (grid=32, 256 thr) ----------------
__global__ void klstm_gates(const float* __restrict__ action, const float* __restrict__ ae_w,
                            const float* __restrict__ ae_b, const float* __restrict__ h0,
                            const float* __restrict__ w_ih, const float* __restrict__ w_hh,
                            const float* __restrict__ b_ih, const float* __restrict__ b_hh) {
    __shared__ float xs[HIDN], h0s[HIDN];
    int tid = threadIdx.x;
    if (tid < HIDN) {
        float acc = ae_b[tid];
#pragma unroll
        for (int j = 0; j < NACT; j++) acc = fmaf(ae_w[tid * NACT + j], action[j], acc);
        xs[tid]  = acc;
        h0s[tid] = h0[tid];
    }
    if (blockIdx.x == 0 && tid == 0) g_smax = (int)0x80000000; // INT_MIN init for atomicMax
    __syncthreads();
    int wid = tid >> 5, lane = tid & 31;
#pragma unroll
    for (int rr = 0; rr < 4; rr++) {
        int r = blockIdx.x * 32 + wid * 4 + rr;
        const float* wi = w_ih + (size_t)r * HIDN;
        const float* wh = w_hh + (size_t)r * HIDN;
        float acc = 0.f;
        for (int j = lane; j < HIDN; j += 32)
            acc = fmaf(wi[j], xs[j], fmaf(wh[j], h0s[j], acc));
#pragma unroll
        for (int s = 16; s; s >>= 1) acc += __shfl_xor_sync(0xffffffffu, acc, s);
        if (lane == 0) g_gates[r] = acc + b_ih[r] + b_hh[r];
    }
}

// ---------------- kernel A2: LSTM cell; writes h,c to out ----------------
__global__ void klstm_cell(const float* __restrict__ c0, float* __restrict__ out) {
    int t = threadIdx.x; // 256 threads
    float gi = g_gates[t], gf = g_gates[HIDN + t], gg = g_gates[2 * HIDN + t], go = g_gates[3 * HIDN + t];
    float si = 1.f / (1.f + expf(-gi));
    float sf = 1.f / (1.f + expf(-gf));
    float so = 1.f / (1.f + expf(-go));
    float c = sf * c0[t] + si * tanhf(gg);
    float h = so * tanhf(c);
    g_h[t] = h; g_c[t] = c;
    out[4 + t]        = h;
    out[4 + HIDN + t] = c;
}

// ---------------- main kernel smem layout (dynamic) ----------------
// sft OVERLAYS simg+sw1 (both dead after GEMM1; extra barrier enforces it)
#define OFF_FT   0                     // 128 x 136 bf16  = 34816 (overlays IMG+W1)
#define OFF_IMG  0                     // 64  x 136 bf16  = 17408
#define OFF_W1   17408                 // 128 x 72  bf16  = 18432 (ends 35840)
#define OFF_IA   35840                 // 128 x 136 bf16  = 34816 (ends 70656)
#define OFF_SP   70656                 // 4 x 128 f32     = 2048
#define OFF_CB   72704                 // 128 f32
#define OFF_IABV 73216                 // 128 f32
#define OFF_FA   73728                 // 128 f32
#define OFF_RED  74240                 // 16 f32
#define DSMEM_B  74304

// 16x8x16 bf16 mma, A row-major (from ldmatrix), B col-major (from ldmatrix.trans)
template <int K>
__device__ __forceinline__ void gemm_tile(
    float (&acc)[2][8][4], unsigned Abase, int AstrideB, unsigned Bbase,
    int mrow0, int ncol0, int a_row, int a_koff, int b_row, int b_col)
{
#pragma unroll
    for (int k0 = 0; k0 < K; k0 += 16) {
        unsigned a[2][4];
#pragma unroll
        for (int mt = 0; mt < 2; mt++) {
            unsigned addr = Abase + (unsigned)((mrow0 + mt * 16 + a_row) * AstrideB + (k0 + a_koff) * 2);
            asm volatile("ldmatrix.sync.aligned.m8n8.x4.shared.b16 {%0,%1,%2,%3}, [%4];"
                         : "=r"(a[mt][0]), "=r"(a[mt][1]), "=r"(a[mt][2]), "=r"(a[mt][3]) : "r"(addr));
        }
        unsigned b[4][4];
#pragma unroll
        for (int np = 0; np < 4; np++) {
            unsigned addr = Bbase + (unsigned)((k0 + b_row) * 272 + (ncol0 + np * 16 + b_col) * 2);
            asm volatile("ldmatrix.sync.aligned.m8n8.x4.trans.shared.b16 {%0,%1,%2,%3}, [%4];"
                         : "=r"(b[np][0]), "=r"(b[np][1]), "=r"(b[np][2]), "=r"(b[np][3]) : "r"(addr));
        }
#pragma unroll
        for (int mt = 0; mt < 2; mt++)
#pragma unroll
            for (int nt = 0; nt < 8; nt++) {
                int np = nt >> 1;
                unsigned b0 = (nt & 1) ? b[np][1] : b[np][0];
                unsigned b1 = (nt & 1) ? b[np][3] : b[np][2];
                asm volatile(
                    "mma.sync.aligned.m16n8k16.row.col.f32.bf16.bf16.f32 "
                    "{%0,%1,%2,%3}, {%4,%5,%6,%7}, {%8,%9}, {%0,%1,%2,%3};"
                    : "+f"(acc[mt][nt][0]), "+f"(acc[mt][nt][1]), "+f"(acc[mt][nt][2]), "+f"(acc[mt][nt][3])
                    : "r"(a[mt][0]), "r"(a[mt][1]), "r"(a[mt][2]), "r"(a[mt][3]), "r"(b0), "r"(b1));
            }
    }
}

// ---------------- kernel B: feat -> att1 -> scores (grid=2048, 256 thr, 2 CTA/SM) --------
__global__ void __launch_bounds__(256, 2) kmain(const float* __restrict__ img,
                                                const float* __restrict__ conv_b,
                                                const float* __restrict__ ia_b,
                                                const float* __restrict__ fa_w) {
    extern __shared__ char sm[];
    __nv_bfloat162* simg = (__nv_bfloat162*)(sm + OFF_IMG);
    __nv_bfloat162* sw1  = (__nv_bfloat162*)(sm + OFF_W1);
    __nv_bfloat162* sia  = (__nv_bfloat162*)(sm + OFF_IA);
    __nv_bfloat162* sft  = (__nv_bfloat162*)(sm + OFF_FT);
    float* spart = (float*)(sm + OFF_SP);
    float* cb    = (float*)(sm + OFF_CB);
    float* iab   = (float*)(sm + OFF_IABV);
    float* fav   = (float*)(sm + OFF_FA);
    float* red   = (float*)(sm + OFF_RED);

    int tid = threadIdx.x;
    int n0  = blockIdx.x * 128;

    // ---- fill smem ----
    {   // img tile (64 x 128 f32 -> bf16), row stride 136 elems (68 words)
        const float* ib = img + n0;
        for (int i = tid; i < 64 * 64; i += 256) {
            int c = i >> 6, mw = i & 63;
            float2 v = *(const float2*)(ib + (size_t)c * NPOS + 2 * mw);
            __nv_bfloat162 b; b.x = __float2bfloat16_rn(v.x); b.y = __float2bfloat16_rn(v.y);
            simg[c * 68 + mw] = b;
        }
        for (int i = tid; i < 128 * 32; i += 256) { // conv_w bf16, stride 72 (36 words)
            int r = i >> 5, kw = i & 31;
            sw1[r * 36 + kw] = *(const __nv_bfloat162*)(g_w1b + r * CDIM + 2 * kw);
        }
        for (int i = tid; i < 128 * 64; i += 256) { // ia_w bf16, stride 136
            int r = i >> 6, kw = i & 63;
            sia[r * 68 + kw] = *(const __nv_bfloat162*)(g_iawb + r * ADIM + 2 * kw);
        }
        if (tid < 128) { cb[tid] = conv_b[tid]; iab[tid] = ia_b[tid]; fav[tid] = fa_w[tid]; }
    }
    __syncthreads();

    int wid = tid >> 5, lane = tid & 31;
    int mrow0 = (wid >> 1) * 32, ncol0 = (wid & 1) * 64;
    int lrow  = lane & 7;
    int a_row  = lrow + ((lane >> 3) & 1) * 8;
    int a_koff = (lane >> 4) * 8;
    int b_row  = lrow + (lane >> 4) * 8;
    int b_col  = ((lane >> 3) & 1) * 8;
    int g = lane >> 2, t = lane & 3;

    float acc[2][8][4] = {};

    // GEMM1: Feat^T (128 x 128) = conv_w (128x64) * img (64x128)
    gemm_tile<64>(acc, s2u(sw1), 144, s2u(simg), mrow0, ncol0, a_row, a_koff, b_row, b_col);

    __syncthreads();   // simg/sw1 dead beyond this point; sft overlays them

    // epilogue 1: +bias, relu, write bf16 Feat^T to smem; re-zero acc
#pragma unroll
    for (int mt = 0; mt < 2; mt++) {
        int r0 = mrow0 + mt * 16 + g, r1 = r0 + 8;
        float cb0 = cb[r0], cb1 = cb[r1];
#pragma unroll
        for (int nt = 0; nt < 8; nt++) {
            int col0 = ncol0 + nt * 8 + 2 * t;
            float v00 = fmaxf(acc[mt][nt][0] + cb0, 0.f);
            float v01 = fmaxf(acc[mt][nt][1] + cb0, 0.f);
            float v10 = fmaxf(acc[mt][nt][2] + cb1, 0.f);
            float v11 = fmaxf(acc[mt][nt][3] + cb1, 0.f);
            __nv_bfloat162 p0; p0.x = __float2bfloat16_rn(v00); p0.y = __float2bfloat16_rn(v01);
            __nv_bfloat162 p1; p1.x = __float2bfloat16_rn(v10); p1.y = __float2bfloat16_rn(v11);
            sft[r0 * 68 + (col0 >> 1)] = p0;
            sft[r1 * 68 + (col0 >> 1)] = p1;
            acc[mt][nt][0] = acc[mt][nt][1] = acc[mt][nt][2] = acc[mt][nt][3] = 0.f;
        }
    }
    __syncthreads();

    // copy Feat^T tile to global scratch (coalesced 32-bit)
    {
        const unsigned* ftw = (const unsigned*)(sm + OFF_FT);
        for (int i = tid; i < 128 * 64; i += 256) {
            int r = i >> 6, cw = i & 63;
            ((unsigned*)(g_featT + (size_t)r * NPOS + n0))[cw] = ftw[r * 68 + cw];
        }
    }

    // GEMM2: att1^T (128 x 128) = ia_w (128x128) * Feat^T
    gemm_tile<128>(acc, s2u(sia), 272, s2u(sft), mrow0, ncol0, a_row, a_koff, b_row, b_col);

    // epilogue 2: +bias, relu, multiply by fa_w[a], column-sum -> scores
    float sv[16];
#pragma unroll
    for (int k = 0; k < 16; k++) sv[k] = 0.f;
#pragma unroll
    for (int mt = 0; mt < 2; mt++) {
        int r0 = mrow0 + mt * 16 + g, r1 = r0 + 8;
        float ib0 = iab[r0], ib1 = iab[r1], f0 = fav[r0], f1 = fav[r1];
#pragma unroll
        for (int nt = 0; nt < 8; nt++) {
            float v00 = fmaxf(acc[mt][nt][0] + ib0, 0.f);
            float v01 = fmaxf(acc[mt][nt][1] + ib0, 0.f);
            float v10 = fmaxf(acc[mt][nt][2] + ib1, 0.f);
            float v11 = fmaxf(acc[mt][nt][3] + ib1, 0.f);
            sv[2 * nt]     += f0 * v00 + f1 * v10;
            sv[2 * nt + 1] += f0 * v01 + f1 * v11;
        }
    }
#pragma unroll
    for (int k = 0; k < 16; k++) {
        sv[k] += __shfl_xor_sync(0xffffffffu, sv[k], 4);
        sv[k] += __shfl_xor_sync(0xffffffffu, sv[k], 8);
        sv[k] += __shfl_xor_sync(0xffffffffu, sv[k], 16);
    }
    if (lane < 4) { // lanes 0..3 hold totals for their column pairs
        float* sp = spart + (wid >> 1) * 128;
#pragma unroll
        for (int nt = 0; nt < 8; nt++) {
            int c = ncol0 + nt * 8 + 2 * lane;
            sp[c]     = sv[2 * nt];
            sp[c + 1] = sv[2 * nt + 1];
        }
    }
    __syncthreads();
    if (tid < 128) {
        float s = spart[tid] + spart[128 + tid] + spart[256 + tid] + spart[384 + tid];
        g_scores[n0 + tid] = s;
        float m = s;
#pragma unroll
        for (int sh = 16; sh; sh >>= 1) m = fmaxf(m, __shfl_xor_sync(0xffffffffu, m, sh));
        if (lane == 0) red[wid] = m;
    }
    __syncthreads();
    if (tid == 0) {
        float m = fmaxf(fmaxf(red[0], red[1]), fmaxf(red[2], red[3]));
        atomicMax(&g_smax, f2o(m));
    }
}

// ---------------- kernel E: weighted sums (grid=1024, 256 thr) ----------------
__global__ void __launch_bounds__(256) katt() {
    __shared__ float ws[KATT_NP];
    __shared__ float red2[8];
    int tid = threadIdx.x, n0 = blockIdx.x * KATT_NP;
    int wid = tid >> 5, lane = tid & 31;
    float smaxv = o2f(g_smax);
    float w = expf(g_scores[n0 + tid] - smaxv);   // 1 position per thread
    ws[tid] = w;
    float zp = w;
#pragma unroll
    for (int s = 16; s; s >>= 1) zp += __shfl_xor_sync(0xffffffffu, zp, s);
    if (lane == 0) red2[wid] = zp;
    __syncthreads();
    if (tid == 0) {
        float z = 0.f;
#pragma unroll
        for (int ww = 0; ww < 8; ww++) z += red2[ww];
        g_Zpart[blockIdx.x] = z;
    }
    // per-a weighted sums; warp w handles a = w, w+8, ... (16 rows per warp)
    float wv0[4], wv1[4];
#pragma unroll
    for (int i = 0; i < 4; i++) {
        float2 p = *(const float2*)(ws + 2 * (lane + 32 * i));
        wv0[i] = p.x; wv1[i] = p.y;
    }
#pragma unroll 2
    for (int a = wid; a < ADIM; a += 8) {
        const __nv_bfloat162* row = (const __nv_bfloat162*)(g_featT + (size_t)a * NPOS + n0);
        float acc = 0.f;
#pragma unroll
        for (int i = 0; i < 4; i++) {
            __nv_bfloat162 v = row[lane + 32 * i];
            acc = fmaf(__low2float(v), wv0[i], fmaf(__high2float(v), wv1[i], acc));
        }
#pragma unroll
        for (int s = 16; s; s >>= 1) acc += __shfl_xor_sync(0xffffffffu, acc, s);
        if (lane == 0) g_Upart[blockIdx.x * ADIM + a] = acc;
    }
}

// ---------------- kernel F: final reduce + logits (1 block, 1024 thr) ----------------
__global__ void __launch_bounds__(1024) kfinal(const float* __restrict__ actor_w,
                                               const float* __restrict__ actor_b,
                                               float* __restrict__ out) {
    __shared__ float part[8][ADIM];
    __shared__ float ao[ADIM];
    __shared__ float zsh;
    int tid = threadIdx.x;
    if (tid < 32) {
        float z = 0.f;
        for (int b = tid; b < KATT_BLKS; b += 32) z += g_Zpart[b];
#pragma unroll
        for (int s = 16; s; s >>= 1) z += __shfl_xor_sync(0xffffffffu, z, s);
        if (tid == 0) zsh = z;
    }
    // 8-way split reduction of U over 1024 block-partials (coalesced)
    {
        int a = tid & (ADIM - 1), c = tid >> 7;   // 8 chunks of 128 blocks
        float u = 0.f;
        for (int j = 0; j < KATT_BLKS / 8; j++)
            u += g_Upart[(size_t)(c * (KATT_BLKS / 8) + j) * ADIM + a];
        part[c][a] = u;
    }
    __syncthreads();
    if (tid < ADIM) {
        float s = 0.f;
#pragma unroll
        for (int c = 0; c < 8; c++) s += part[c][tid];
        ao[tid] = s / zsh;
    }
    __syncthreads();
    int wid = tid >> 5, lane = tid & 31;
    if (wid < 4) {
        const float* wrow = actor_w + (size_t)wid * (ADIM + HIDN);
        float acc = 0.f;
        for (int j = lane; j < ADIM + HIDN; j += 32) {
            float v = (j < ADIM) ? ao[j] : g_h[j - ADIM];
            acc = fmaf(wrow[j], v, acc);
        }
#pragma unroll
        for (int s = 16; s; s >>= 1) acc += __shfl_xor_sync(0xffffffffu, acc, s);
        if (lane == 0) out[wid] = acc + actor_b[wid];
    }
}

// ---------------- launcher ----------------
extern "C" void kernel_launch(void* const* d_in, const int* in_sizes, int n_in,
                              void* d_out, int out_size) {
    (void)in_sizes; (void)n_in; (void)out_size;
    const float* img     = (const float*)d_in[0];
    const float* action  = (const float*)d_in[1];
    const float* h0      = (const float*)d_in[2];
    const float* c0      = (const float*)d_in[3];
    const float* conv_w  = (const float*)d_in[4];
    const float* conv_b  = (const float*)d_in[5];
    const float* ae_w    = (const float*)d_in[6];
    const float* ae_b    = (const float*)d_in[7];
    const float* ia_w    = (const float*)d_in[8];
    const float* ia_b    = (const float*)d_in[9];
    // d_in[10] ha_w, d_in[11] ha_b, d_in[13] fa_b: constants cancel in softmax
    const float* fa_w    = (const float*)d_in[12];
    const float* w_ih    = (const float*)d_in[14];
    const float* w_hh    = (const float*)d_in[15];
    const float* b_ih    = (const float*)d_in[16];
    const float* b_hh    = (const float*)d_in[17];
    const float* actor_w = (const float*)d_in[18];
    const float* actor_b = (const float*)d_in[19];
    float* out = (float*)d_out;

    cudaFuncSetAttribute(kmain, cudaFuncAttributeMaxDynamicSharedMemorySize, DSMEM_B);
    cudaFuncSetAttribute(kmain, cudaFuncAttributePreferredSharedMemoryCarveout, 100);

    kweights<<<64, 256>>>(conv_w, ia_w);
    klstm_gates<<<32, 256>>>(action, ae_w, ae_b, h0, w_ih, w_hh, b_ih, b_hh);
    klstm_cell<<<1, 256>>>(c0, out);
    kmain<<<NPOS / 128, 256, DSMEM_B>>>(img, conv_b, ia_b, fa_w);
    katt<<<KATT_BLKS, 256>>>();
    kfinal<<<1, 1024>>>(actor_w, actor_b, out);
}

// round 16
// speedup vs baseline: 1.2911x; 1.1908x over previous
#include <cuda_runtime.h>
#include <cuda_bf16.h>

// ---------------- problem constants ----------------
#define NPOS  (512*512)   // 262144 spatial positions
#define CDIM  64
#define ADIM  128
#define HIDN  256
#define NACT  4

#define KATT_BLKS 1024
#define KATT_NP   256     // positions per katt block

// ---------------- scratch (device globals; no allocation) ----------------
__device__ __nv_bfloat16 g_featT[(size_t)ADIM * NPOS]; // [a][n]  64 MB
__device__ float g_scores[NPOS];
__device__ int   g_smax;                   // ordered-int float max
__device__ float g_gates[4 * HIDN];
__device__ float g_h[HIDN];
__device__ float g_c[HIDN];
__device__ __nv_bfloat16 g_w1b[ADIM * CDIM];
__device__ __nv_bfloat16 g_iawb[ADIM * ADIM];
__device__ float g_Upart[KATT_BLKS * ADIM];
__device__ float g_Zpart[KATT_BLKS];

// ordered-int mapping for atomicMax on float (monotone, deterministic)
__device__ __forceinline__ int f2o(float f) {
    int i = __float_as_int(f);
    return i >= 0 ? i : (i ^ 0x7FFFFFFF);
}
__device__ __forceinline__ float o2f(int o) {
    return __int_as_float(o >= 0 ? o : (o ^ 0x7FFFFFFF));
}

__device__ __forceinline__ unsigned s2u(const void* p) {
    return (unsigned)__cvta_generic_to_shared(p);
}

// ---------------- kernel W: convert weights to bf16 ----------------
__global__ void kweights(const float* __restrict__ conv_w, const float* __restrict__ ia_w) {
    int idx = blockIdx.x * blockDim.x + threadIdx.x;
    if (idx < ADIM * CDIM) g_w1b[idx]  = __float2bfloat16(conv_w[idx]);
    if (idx < ADIM * ADIM) g_iawb[idx] = __float2bfloat16(ia_w[idx]);
}

// ---------------- kernel A1: LSTM gates (grid=32, 256 thr) ----------------
__global__ void klstm_gates(const float* __restrict__ action, const float* __restrict__ ae_w,
                            const float* __restrict__ ae_b, const float* __restrict__ h0,
                            const float* __restrict__ w_ih, const float* __restrict__ w_hh,
                            const float* __restrict__ b_ih, const float* __restrict__ b_hh) {
    __shared__ float xs[HIDN], h0s[HIDN];
    int tid = threadIdx.x;
    if (tid < HIDN) {
        float acc = ae_b[tid];
#pragma unroll
        for (int j = 0; j < NACT; j++) acc = fmaf(ae_w[tid * NACT + j], action[j], acc);
        xs[tid]  = acc;
        h0s[tid] = h0[tid];
    }
    if (blockIdx.x == 0 && tid == 0) g_smax = (int)0x80000000; // INT_MIN init for atomicMax
    __syncthreads();
    int wid = tid >> 5, lane = tid & 31;
#pragma unroll
    for (int rr = 0; rr < 4; rr++) {
        int r = blockIdx.x * 32 + wid * 4 + rr;
        const float* wi = w_ih + (size_t)r * HIDN;
        const float* wh = w_hh + (size_t)r * HIDN;
        float acc = 0.f;
        for (int j = lane; j < HIDN; j += 32)
            acc = fmaf(wi[j], xs[j], fmaf(wh[j], h0s[j], acc));
#pragma unroll
        for (int s = 16; s; s >>= 1) acc += __shfl_xor_sync(0xffffffffu, acc, s);
        if (lane == 0) g_gates[r] = acc + b_ih[r] + b_hh[r];
    }
}

// ---------------- kernel A2: LSTM cell; writes h,c to out ----------------
__global__ void klstm_cell(const float* __restrict__ c0, float* __restrict__ out) {
    int t = threadIdx.x; // 256 threads
    float gi = g_gates[t], gf = g_gates[HIDN + t], gg = g_gates[2 * HIDN + t], go = g_gates[3 * HIDN + t];
    float si = 1.f / (1.f + expf(-gi));
    float sf = 1.f / (1.f + expf(-gf));
    float so = 1.f / (1.f + expf(-go));
    float c = sf * c0[t] + si * tanhf(gg);
    float h = so * tanhf(c);
    g_h[t] = h; g_c[t] = c;
    out[4 + t]        = h;
    out[4 + HIDN + t] = c;
}

// ---------------- main kernel smem layout (dynamic) ----------------
// sft OVERLAYS simg+sw1 (both dead after GEMM1; extra barrier enforces it)
#define OFF_FT   0                     // 128 x 136 bf16  = 34816 (overlays IMG+W1)
#define OFF_IMG  0                     // 64  x 136 bf16  = 17408
#define OFF_W1   17408                 // 128 x 72  bf16  = 18432 (ends 35840)
#define OFF_IA   35840                 // 128 x 136 bf16  = 34816 (ends 70656)
#define OFF_SP   70656                 // 4 x 128 f32     = 2048
#define OFF_CB   72704                 // 128 f32
#define OFF_IABV 73216                 // 128 f32
#define OFF_FA   73728                 // 128 f32
#define OFF_RED  74240                 // 16 f32
#define DSMEM_B  74304

// 16x8x16 bf16 mma, A row-major (ldmatrix), B col-major (ldmatrix.trans)
// Warp tile: 32 (M) x 32 (N): acc[2][4][4] = 32 regs.
template <int K>
__device__ __forceinline__ void gemm_tile(
    float (&acc)[2][4][4], unsigned Abase, int AstrideB, unsigned Bbase,
    int mrow0, int ncol0, int a_row, int a_koff, int b_row, int b_col)
{
#pragma unroll
    for (int k0 = 0; k0 < K; k0 += 16) {
        unsigned a[2][4];
#pragma unroll
        for (int mt = 0; mt < 2; mt++) {
            unsigned addr = Abase + (unsigned)((mrow0 + mt * 16 + a_row) * AstrideB + (k0 + a_koff) * 2);
            asm volatile("ldmatrix.sync.aligned.m8n8.x4.shared.b16 {%0,%1,%2,%3}, [%4];"
                         : "=r"(a[mt][0]), "=r"(a[mt][1]), "=r"(a[mt][2]), "=r"(a[mt][3]) : "r"(addr));
        }
        unsigned b[2][4];
#pragma unroll
        for (int np = 0; np < 2; np++) {
            unsigned addr = Bbase + (unsigned)((k0 + b_row) * 272 + (ncol0 + np * 16 + b_col) * 2);
            asm volatile("ldmatrix.sync.aligned.m8n8.x4.trans.shared.b16 {%0,%1,%2,%3}, [%4];"
                         : "=r"(b[np][0]), "=r"(b[np][1]), "=r"(b[np][2]), "=r"(b[np][3]) : "r"(addr));
        }
#pragma unroll
        for (int mt = 0; mt < 2; mt++)
#pragma unroll
            for (int nt = 0; nt < 4; nt++) {
                int np = nt >> 1;
                unsigned b0 = (nt & 1) ? b[np][1] : b[np][0];
                unsigned b1 = (nt & 1) ? b[np][3] : b[np][2];
                asm volatile(
                    "mma.sync.aligned.m16n8k16.row.col.f32.bf16.bf16.f32 "
                    "{%0,%1,%2,%3}, {%4,%5,%6,%7}, {%8,%9}, {%0,%1,%2,%3};"
                    : "+f"(acc[mt][nt][0]), "+f"(acc[mt][nt][1]), "+f"(acc[mt][nt][2]), "+f"(acc[mt][nt][3])
                    : "r"(a[mt][0]), "r"(a[mt][1]), "r"(a[mt][2]), "r"(a[mt][3]), "r"(b0), "r"(b1));
            }
    }
}

// ---------------- kernel B: feat -> att1 -> scores (grid=2048, 512 thr, 2 CTA/SM) --------
__global__ void __launch_bounds__(512, 2) kmain(const float* __restrict__ img,
                                                const float* __restrict__ conv_b,
                                                const float* __restrict__ ia_b,
                                                const float* __restrict__ fa_w) {
    extern __shared__ char sm[];
    __nv_bfloat162* simg = (__nv_bfloat162*)(sm + OFF_IMG);
    __nv_bfloat162* sw1  = (__nv_bfloat162*)(sm + OFF_W1);
    __nv_bfloat162* sia  = (__nv_bfloat162*)(sm + OFF_IA);
    __nv_bfloat162* sft  = (__nv_bfloat162*)(sm + OFF_FT);
    float* spart = (float*)(sm + OFF_SP);
    float* cb    = (float*)(sm + OFF_CB);
    float* iab   = (float*)(sm + OFF_IABV);
    float* fav   = (float*)(sm + OFF_FA);
    float* red   = (float*)(sm + OFF_RED);

    int tid = threadIdx.x;
    int n0  = blockIdx.x * 128;

    // ---- fill smem ----
    {   // img tile (64 x 128 f32 -> bf16), row stride 136 elems (68 words)
        const float* ib = img + n0;
        for (int i = tid; i < 64 * 64; i += 512) {
            int c = i >> 6, mw = i & 63;
            float2 v = *(const float2*)(ib + (size_t)c * NPOS + 2 * mw);
            __nv_bfloat162 b; b.x = __float2bfloat16_rn(v.x); b.y = __float2bfloat16_rn(v.y);
            simg[c * 68 + mw] = b;
        }
        for (int i = tid; i < 128 * 32; i += 512) { // conv_w bf16, stride 72 (36 words)
            int r = i >> 5, kw = i & 31;
            sw1[r * 36 + kw] = *(const __nv_bfloat162*)(g_w1b + r * CDIM + 2 * kw);
        }
        for (int i = tid; i < 128 * 64; i += 512) { // ia_w bf16, stride 136
            int r = i >> 6, kw = i & 63;
            sia[r * 68 + kw] = *(const __nv_bfloat162*)(g_iawb + r * ADIM + 2 * kw);
        }
        if (tid < 128) { cb[tid] = conv_b[tid]; iab[tid] = ia_b[tid]; fav[tid] = fa_w[tid]; }
    }
    __syncthreads();

    int wid = tid >> 5, lane = tid & 31;
    int mrow0 = (wid >> 2) * 32, ncol0 = (wid & 3) * 32;   // 4x4 warp grid, 32x32 tiles
    int lrow  = lane & 7;
    int a_row  = lrow + ((lane >> 3) & 1) * 8;
    int a_koff = (lane >> 4) * 8;
    int b_row  = lrow + (lane >> 4) * 8;
    int b_col  = ((lane >> 3) & 1) * 8;
    int g = lane >> 2, t = lane & 3;

    float acc[2][4][4] = {};

    // GEMM1: Feat^T (128 x 128) = conv_w (128x64) * img (64x128)
    gemm_tile<64>(acc, s2u(sw1), 144, s2u(simg), mrow0, ncol0, a_row, a_koff, b_row, b_col);

    __syncthreads();   // simg/sw1 dead beyond this point; sft overlays them

    // epilogue 1: +bias, relu, write bf16 Feat^T to smem; re-zero acc
#pragma unroll
    for (int mt = 0; mt < 2; mt++) {
        int r0 = mrow0 + mt * 16 + g, r1 = r0 + 8;
        float cb0 = cb[r0], cb1 = cb[r1];
#pragma unroll
        for (int nt = 0; nt < 4; nt++) {
            int col0 = ncol0 + nt * 8 + 2 * t;
            float v00 = fmaxf(acc[mt][nt][0] + cb0, 0.f);
            float v01 = fmaxf(acc[mt][nt][1] + cb0, 0.f);
            float v10 = fmaxf(acc[mt][nt][2] + cb1, 0.f);
            float v11 = fmaxf(acc[mt][nt][3] + cb1, 0.f);
            __nv_bfloat162 p0; p0.x = __float2bfloat16_rn(v00); p0.y = __float2bfloat16_rn(v01);
            __nv_bfloat162 p1; p1.x = __float2bfloat16_rn(v10); p1.y = __float2bfloat16_rn(v11);
            sft[r0 * 68 + (col0 >> 1)] = p0;
            sft[r1 * 68 + (col0 >> 1)] = p1;
            acc[mt][nt][0] = acc[mt][nt][1] = acc[mt][nt][2] = acc[mt][nt][3] = 0.f;
        }
    }
    __syncthreads();

    // copy Feat^T tile to global scratch (coalesced 32-bit)
    {
        const unsigned* ftw = (const unsigned*)(sm + OFF_FT);
        for (int i = tid; i < 128 * 64; i += 512) {
            int r = i >> 6, cw = i & 63;
            ((unsigned*)(g_featT + (size_t)r * NPOS + n0))[cw] = ftw[r * 68 + cw];
        }
    }

    // GEMM2: att1^T (128 x 128) = ia_w (128x128) * Feat^T
    gemm_tile<128>(acc, s2u(sia), 272, s2u(sft), mrow0, ncol0, a_row, a_koff, b_row, b_col);

    // epilogue 2: +bias, relu, multiply by fa_w[a], column-sum -> scores
    float sv[8];
#pragma unroll
    for (int k = 0; k < 8; k++) sv[k] = 0.f;
#pragma unroll
    for (int mt = 0; mt < 2; mt++) {
        int r0 = mrow0 + mt * 16 + g, r1 = r0 + 8;
        float ib0 = iab[r0], ib1 = iab[r1], f0 = fav[r0], f1 = fav[r1];
#pragma unroll
        for (int nt = 0; nt < 4; nt++) {
            float v00 = fmaxf(acc[mt][nt][0] + ib0, 0.f);
            float v01 = fmaxf(acc[mt][nt][1] + ib0, 0.f);
            float v10 = fmaxf(acc[mt][nt][2] + ib1, 0.f);
            float v11 = fmaxf(acc[mt][nt][3] + ib1, 0.f);
            sv[2 * nt]     += f0 * v00 + f1 * v10;
            sv[2 * nt + 1] += f0 * v01 + f1 * v11;
        }
    }
#pragma unroll
    for (int k = 0; k < 8; k++) {
        sv[k] += __shfl_xor_sync(0xffffffffu, sv[k], 4);
        sv[k] += __shfl_xor_sync(0xffffffffu, sv[k], 8);
        sv[k] += __shfl_xor_sync(0xffffffffu, sv[k], 16);
    }
    if (lane < 4) { // lanes 0..3 hold totals for their column pairs
        float* sp = spart + (wid >> 2) * 128;   // 4 warp-row groups
#pragma unroll
        for (int nt = 0; nt < 4; nt++) {
            int c = ncol0 + nt * 8 + 2 * lane;
            sp[c]     = sv[2 * nt];
            sp[c + 1] = sv[2 * nt + 1];
        }
    }
    __syncthreads();
    if (tid < 128) {
        float s = spart[tid] + spart[128 + tid] + spart[256 + tid] + spart[384 + tid];
        g_scores[n0 + tid] = s;
        float m = s;
#pragma unroll
        for (int sh = 16; sh; sh >>= 1) m = fmaxf(m, __shfl_xor_sync(0xffffffffu, m, sh));
        if (lane == 0) red[wid] = m;
    }
    __syncthreads();
    if (tid == 0) {
        float m = fmaxf(fmaxf(red[0], red[1]), fmaxf(red[2], red[3]));
        atomicMax(&g_smax, f2o(m));
    }
}

// ---------------- kernel E: weighted sums (grid=1024, 256 thr) ----------------
__global__ void __launch_bounds__(256) katt() {
    __shared__ float ws[KATT_NP];
    __shared__ float red2[8];
    int tid = threadIdx.x, n0 = blockIdx.x * KATT_NP;
    int wid = tid >> 5, lane = tid & 31;
    float smaxv = o2f(g_smax);
    float w = expf(g_scores[n0 + tid] - smaxv);   // 1 position per thread
    ws[tid] = w;
    float zp = w;
#pragma unroll
    for (int s = 16; s; s >>= 1) zp += __shfl_xor_sync(0xffffffffu, zp, s);
    if (lane == 0) red2[wid] = zp;
    __syncthreads();
    if (tid == 0) {
        float z = 0.f;
#pragma unroll
        for (int ww = 0; ww < 8; ww++) z += red2[ww];
        g_Zpart[blockIdx.x] = z;
    }
    // per-a weighted sums; warp w handles a = w, w+8, ... (16 rows per warp)
    float wv0[4], wv1[4];
#pragma unroll
    for (int i = 0; i < 4; i++) {
        float2 p = *(const float2*)(ws + 2 * (lane + 32 * i));
        wv0[i] = p.x; wv1[i] = p.y;
    }
#pragma unroll 2
    for (int a = wid; a < ADIM; a += 8) {
        const __nv_bfloat162* row = (const __nv_bfloat162*)(g_featT + (size_t)a * NPOS + n0);
        float acc = 0.f;
#pragma unroll
        for (int i = 0; i < 4; i++) {
            __nv_bfloat162 v = row[lane + 32 * i];
            acc = fmaf(__low2float(v), wv0[i], fmaf(__high2float(v), wv1[i], acc));
        }
#pragma unroll
        for (int s = 16; s; s >>= 1) acc += __shfl_xor_sync(0xffffffffu, acc, s);
        if (lane == 0) g_Upart[blockIdx.x * ADIM + a] = acc;
    }
}

// ---------------- kernel F: final reduce + logits (1 block, 1024 thr) ----------------
__global__ void __launch_bounds__(1024) kfinal(const float* __restrict__ actor_w,
                                               const float* __restrict__ actor_b,
                                               float* __restrict__ out) {
    __shared__ float part[8][ADIM];
    __shared__ float ao[ADIM];
    __shared__ float zsh;
    int tid = threadIdx.x;
    if (tid < 32) {
        float z = 0.f;
        for (int b = tid; b < KATT_BLKS; b += 32) z += g_Zpart[b];
#pragma unroll
        for (int s = 16; s; s >>= 1) z += __shfl_xor_sync(0xffffffffu, z, s);
        if (tid == 0) zsh = z;
    }
    // 8-way split reduction of U over 1024 block-partials (coalesced)
    {
        int a = tid & (ADIM - 1), c = tid >> 7;   // 8 chunks of 128 blocks
        float u = 0.f;
        for (int j = 0; j < KATT_BLKS / 8; j++)
            u += g_Upart[(size_t)(c * (KATT_BLKS / 8) + j) * ADIM + a];
        part[c][a] = u;
    }
    __syncthreads();
    if (tid < ADIM) {
        float s = 0.f;
#pragma unroll
        for (int c = 0; c < 8; c++) s += part[c][tid];
        ao[tid] = s / zsh;
    }
    __syncthreads();
    int wid = tid >> 5, lane = tid & 31;
    if (wid < 4) {
        const float* wrow = actor_w + (size_t)wid * (ADIM + HIDN);
        float acc = 0.f;
        for (int j = lane; j < ADIM + HIDN; j += 32) {
            float v = (j < ADIM) ? ao[j] : g_h[j - ADIM];
            acc = fmaf(wrow[j], v, acc);
        }
#pragma unroll
        for (int s = 16; s; s >>= 1) acc += __shfl_xor_sync(0xffffffffu, acc, s);
        if (lane == 0) out[wid] = acc + actor_b[wid];
    }
}

// ---------------- launcher ----------------
extern "C" void kernel_launch(void* const* d_in, const int* in_sizes, int n_in,
                              void* d_out, int out_size) {
    (void)in_sizes; (void)n_in; (void)out_size;
    const float* img     = (const float*)d_in[0];
    const float* action  = (const float*)d_in[1];
    const float* h0      = (const float*)d_in[2];
    const float* c0      = (const float*)d_in[3];
    const float* conv_w  = (const float*)d_in[4];
    const float* conv_b  = (const float*)d_in[5];
    const float* ae_w    = (const float*)d_in[6];
    const float* ae_b    = (const float*)d_in[7];
    const float* ia_w    = (const float*)d_in[8];
    const float* ia_b    = (const float*)d_in[9];
    // d_in[10] ha_w, d_in[11] ha_b, d_in[13] fa_b: constants cancel in softmax
    const float* fa_w    = (const float*)d_in[12];
    const float* w_ih    = (const float*)d_in[14];
    const float* w_hh    = (const float*)d_in[15];
    const float* b_ih    = (const float*)d_in[16];
    const float* b_hh    = (const float*)d_in[17];
    const float* actor_w = (const float*)d_in[18];
    const float* actor_b = (const float*)d_in[19];
    float* out = (float*)d_out;

    cudaFuncSetAttribute(kmain, cudaFuncAttributeMaxDynamicSharedMemorySize, DSMEM_B);
    cudaFuncSetAttribute(kmain, cudaFuncAttributePreferredSharedMemoryCarveout, 100);

    kweights<<<64, 256>>>(conv_w, ia_w);
    klstm_gates<<<32, 256>>>(action, ae_w, ae_b, h0, w_ih, w_hh, b_ih, b_hh);
    klstm_cell<<<1, 256>>>(c0, out);
    kmain<<<NPOS / 128, 512, DSMEM_B>>>(img, conv_b, ia_b, fa_w);
    katt<<<KATT_BLKS, 256>>>();
    kfinal<<<1, 1024>>>(actor_w, actor_b, out);
}